// round 1
// baseline (speedup 1.0000x reference)
#include <cuda_runtime.h>
#include <cuda_bf16.h>

#define B_ 2
#define S_ 2048
#define D_ 1024
#define H_ 16
#define HD_ 64
#define MAXD 1024

// Scratch (allocation-free rule: __device__ globals)
__device__ float g_q[B_*S_*D_];
__device__ float g_k[B_*S_*D_];
__device__ float g_v[B_*S_*D_];
__device__ float g_attn[B_*S_*D_];

// ---------------------------------------------------------------------------
// Tiled fp32 GEMM: C[M,N] = A[M,K] @ W[K,N] (+ bias). M,N mult of 64, K mult of 32.
// 256 threads, BM=BN=64, BK=32, 4x4 micro-tile per thread.
// ---------------------------------------------------------------------------
template<bool HAS_BIAS>
__global__ void gemm64(const float* __restrict__ A, const float* __restrict__ W,
                       const float* __restrict__ bias, float* __restrict__ C,
                       int M, int N, int K)
{
    const int BM = 64, BN = 64, BK = 32;
    __shared__ float As[BK][BM + 4];   // row stride 68 floats (mult of 4 -> float4 ok)
    __shared__ float Bs[BK][BN + 4];

    int tid = threadIdx.x;             // 0..255
    int tx = tid & 15, ty = tid >> 4;
    int rowBase = blockIdx.y * BM;
    int colBase = blockIdx.x * BN;

    float acc[4][4] = {};

    for (int k0 = 0; k0 < K; k0 += BK) {
        #pragma unroll
        for (int i = 0; i < 8; i++) {             // A tile 64x32
            int idx = tid + i * 256;
            int mm = idx >> 5, kk = idx & 31;
            As[kk][mm] = A[(size_t)(rowBase + mm) * K + k0 + kk];
        }
        #pragma unroll
        for (int i = 0; i < 8; i++) {             // W tile 32x64
            int idx = tid + i * 256;
            int kk = idx >> 6, nn = idx & 63;
            Bs[kk][nn] = W[(size_t)(k0 + kk) * N + colBase + nn];
        }
        __syncthreads();

        #pragma unroll
        for (int kk = 0; kk < BK; kk++) {
            float4 a4 = *(const float4*)(&As[kk][ty * 4]);
            float4 b4 = *(const float4*)(&Bs[kk][tx * 4]);
            float a[4] = {a4.x, a4.y, a4.z, a4.w};
            float b[4] = {b4.x, b4.y, b4.z, b4.w};
            #pragma unroll
            for (int i = 0; i < 4; i++)
                #pragma unroll
                for (int j = 0; j < 4; j++)
                    acc[i][j] += a[i] * b[j];
        }
        __syncthreads();
    }

    #pragma unroll
    for (int i = 0; i < 4; i++) {
        int r = rowBase + ty * 4 + i;
        #pragma unroll
        for (int j = 0; j < 4; j++) {
            int c = colBase + tx * 4 + j;
            float v = acc[i][j];
            if (HAS_BIAS) v += bias[c];
            C[(size_t)r * N + c] = v;
        }
    }
}

// ---------------------------------------------------------------------------
// Flash attention with relative-position bias.
// One block = one (b, h, 64-query tile). 256 threads: 4 lanes per query row.
// logits = c1 * (q.k) + c2 * pos_bias[clamp(i-j)+MAXD-1][h]
// ---------------------------------------------------------------------------
__global__ void flash_attn(const float* __restrict__ q,
                           const float* __restrict__ k,
                           const float* __restrict__ v,
                           const float* __restrict__ pb,
                           float* __restrict__ out)
{
    extern __shared__ float sm[];
    const int LD = 68;                 // padded row stride (mult of 4 floats)
    float* Qs = sm;                    // [64][68]
    float* Ks = Qs + 64 * LD;
    float* Vs = Ks + 64 * LD;
    float* Ps = Vs + 64 * LD;

    int tid = threadIdx.x;             // 0..255
    int qr  = tid >> 2;                // query row within tile, 0..63
    int kg  = tid & 3;                 // key/dim group 0..3 (16 each)
    int bh  = blockIdx.y;              // 0..31
    int b   = bh >> 4, h = bh & 15;
    int q0  = blockIdx.x * 64;

    const float c1 = 0.4785533905932738f;   // 1/8 + 64^-0.25
    const float c2 = 0.3535533905932738f;   // 64^-0.25

    // Load Q tile [64 rows x 64 dims]
    #pragma unroll
    for (int i = 0; i < 16; i++) {
        int idx = tid + i * 256;
        int r = idx >> 6, d = idx & 63;
        Qs[r * LD + d] = q[((size_t)(b * S_ + q0 + r)) * D_ + h * HD_ + d];
    }

    float m = -1e30f, l = 0.f;
    float o[16] = {};
    int iq = q0 + qr;

    for (int kt = 0; kt < S_; kt += 64) {
        #pragma unroll
        for (int i = 0; i < 16; i++) {
            int idx = tid + i * 256;
            int r = idx >> 6, d = idx & 63;
            size_t g = ((size_t)(b * S_ + kt + r)) * D_ + h * HD_ + d;
            Ks[r * LD + d] = k[g];
            Vs[r * LD + d] = v[g];
        }
        __syncthreads();

        // scores for this thread's 16 keys
        float s[16];
        float tmax = -1e30f;
        const float4* qrow = (const float4*)(Qs + qr * LD);
        #pragma unroll
        for (int kk = 0; kk < 16; kk++) {
            int kr = kg * 16 + kk;
            const float4* krow = (const float4*)(Ks + kr * LD);
            float acc = 0.f;
            #pragma unroll
            for (int d4 = 0; d4 < 16; d4++) {
                float4 qa = qrow[d4], kb = krow[d4];
                acc += qa.x * kb.x + qa.y * kb.y + qa.z * kb.z + qa.w * kb.w;
            }
            int jj = kt + kr;
            int p = iq - jj;
            p = min(max(p, -(MAXD - 1)), MAXD - 1) + (MAXD - 1);
            float bias = __ldg(&pb[p * H_ + h]);
            float sv = c1 * acc + c2 * bias;
            s[kk] = sv;
            tmax = fmaxf(tmax, sv);
        }
        // row max across the 4 lanes of this query row
        tmax = fmaxf(tmax, __shfl_xor_sync(0xffffffffu, tmax, 1));
        tmax = fmaxf(tmax, __shfl_xor_sync(0xffffffffu, tmax, 2));
        float mnew = fmaxf(m, tmax);
        float corr = __expf(m - mnew);

        float lsum = 0.f;
        #pragma unroll
        for (int kk = 0; kk < 16; kk++) {
            float p = __expf(s[kk] - mnew);
            Ps[qr * LD + kg * 16 + kk] = p;
            lsum += p;
        }
        lsum += __shfl_xor_sync(0xffffffffu, lsum, 1);
        lsum += __shfl_xor_sync(0xffffffffu, lsum, 2);
        l = l * corr + lsum;
        m = mnew;
        #pragma unroll
        for (int i = 0; i < 16; i++) o[i] *= corr;

        __syncthreads();   // Ps complete for all rows; Ks reads done

        // PV accumulate: this thread owns dims [kg*16, kg*16+16) of row qr
        float4* o4 = (float4*)o;
        const float* prow = Ps + qr * LD;
        #pragma unroll 8
        for (int kk = 0; kk < 64; kk++) {
            float p = prow[kk];
            const float4* vrow = (const float4*)(Vs + kk * LD + kg * 16);
            #pragma unroll
            for (int j = 0; j < 4; j++) {
                float4 vv = vrow[j];
                o4[j].x += p * vv.x;
                o4[j].y += p * vv.y;
                o4[j].z += p * vv.z;
                o4[j].w += p * vv.w;
            }
        }
        __syncthreads();   // Vs/Ps reads done before next tile overwrites
    }

    float inv = 1.f / l;
    #pragma unroll
    for (int i = 0; i < 16; i++)
        out[((size_t)(b * S_ + iq)) * D_ + h * HD_ + kg * 16 + i] = o[i] * inv;
}

// ---------------------------------------------------------------------------
extern "C" void kernel_launch(void* const* d_in, const int* in_sizes, int n_in,
                              void* d_out, int out_size)
{
    const float* x  = (const float*)d_in[0];
    const float* Wq = (const float*)d_in[1];
    const float* bq = (const float*)d_in[2];
    const float* Wk = (const float*)d_in[3];
    const float* Wv = (const float*)d_in[4];
    const float* bv = (const float*)d_in[5];
    const float* Wo = (const float*)d_in[6];
    const float* bo = (const float*)d_in[7];
    const float* pb = (const float*)d_in[8];
    float* out = (float*)d_out;

    float *q, *k, *v, *attn;
    cudaGetSymbolAddress((void**)&q,    g_q);
    cudaGetSymbolAddress((void**)&k,    g_k);
    cudaGetSymbolAddress((void**)&v,    g_v);
    cudaGetSymbolAddress((void**)&attn, g_attn);

    const int M = B_ * S_;   // 4096
    dim3 gGrid(D_ / 64, M / 64);   // (16, 64)
    dim3 gBlk(256);

    gemm64<true ><<<gGrid, gBlk>>>(x, Wq, bq, q, M, D_, D_);
    gemm64<false><<<gGrid, gBlk>>>(x, Wk, nullptr, k, M, D_, D_);
    gemm64<true ><<<gGrid, gBlk>>>(x, Wv, bv, v, M, D_, D_);

    int smem = 4 * 64 * 68 * sizeof(float);   // 69632 B
    cudaFuncSetAttribute(flash_attn, cudaFuncAttributeMaxDynamicSharedMemorySize, smem);
    dim3 fGrid(S_ / 64, B_ * H_);   // (32, 32)
    flash_attn<<<fGrid, dim3(256), smem>>>(q, k, v, pb, attn);

    gemm64<true ><<<gGrid, gBlk>>>(attn, Wo, bo, out, M, D_, D_);
}

// round 2
// speedup vs baseline: 3.5645x; 3.5645x over previous
#include <cuda_runtime.h>
#include <cuda_bf16.h>

#define B_ 2
#define S_ 2048
#define D_ 1024
#define H_ 16
#define HD_ 64
#define MAXD 1024

// Scratch (allocation-free rule: __device__ globals)
__device__ float g_q[B_*S_*D_];
__device__ float g_k[B_*S_*D_];
__device__ float g_v[B_*S_*D_];
__device__ float g_attn[B_*S_*D_];

// ---------------------------------------------------------------------------
// Tiled fp32 GEMM: C = A[M,K] @ W[K,N] (+bias). BM=BN=128, BK=16,
// 256 threads, 8x8 micro-tile -> 16 FMA per LDS.128.
// ---------------------------------------------------------------------------
template<bool HAS_BIAS>
__global__ void __launch_bounds__(256, 2)
gemm128(const float* __restrict__ A, const float* __restrict__ W,
        const float* __restrict__ bias, float* __restrict__ C,
        int M, int N, int K)
{
    const int BK = 16;
    __shared__ float As[BK][132];   // A transposed: As[k][m]
    __shared__ float Bs[BK][132];   // natural:      Bs[k][n]

    int tid = threadIdx.x;
    int tx = tid & 15, ty = tid >> 4;
    int rowBase = blockIdx.y * 128;
    int colBase = blockIdx.x * 128;

    float acc[8][8] = {};

    for (int k0 = 0; k0 < K; k0 += BK) {
        #pragma unroll
        for (int i = 0; i < 2; i++) {               // A tile 128x16
            int fi = tid + i * 256;                 // 512 float4s
            int mm = fi >> 2, kq = (fi & 3) * 4;
            float4 a = *(const float4*)&A[(size_t)(rowBase + mm) * K + k0 + kq];
            As[kq+0][mm] = a.x; As[kq+1][mm] = a.y;
            As[kq+2][mm] = a.z; As[kq+3][mm] = a.w;
        }
        #pragma unroll
        for (int i = 0; i < 2; i++) {               // W tile 16x128
            int fi = tid + i * 256;
            int kk = fi >> 5, n4 = (fi & 31) * 4;
            *(float4*)&Bs[kk][n4] = *(const float4*)&W[(size_t)(k0 + kk) * N + colBase + n4];
        }
        __syncthreads();

        #pragma unroll
        for (int kk = 0; kk < BK; kk++) {
            float a[8], b[8];
            *(float4*)&a[0] = *(const float4*)&As[kk][ty * 8];
            *(float4*)&a[4] = *(const float4*)&As[kk][ty * 8 + 4];
            *(float4*)&b[0] = *(const float4*)&Bs[kk][tx * 8];
            *(float4*)&b[4] = *(const float4*)&Bs[kk][tx * 8 + 4];
            #pragma unroll
            for (int i = 0; i < 8; i++)
                #pragma unroll
                for (int j = 0; j < 8; j++)
                    acc[i][j] += a[i] * b[j];
        }
        __syncthreads();
    }

    float bv[8] = {};
    if (HAS_BIAS) {
        *(float4*)&bv[0] = *(const float4*)&bias[colBase + tx * 8];
        *(float4*)&bv[4] = *(const float4*)&bias[colBase + tx * 8 + 4];
    }
    #pragma unroll
    for (int i = 0; i < 8; i++) {
        int r = rowBase + ty * 8 + i;
        float4 o0, o1;
        o0.x = acc[i][0] + bv[0]; o0.y = acc[i][1] + bv[1];
        o0.z = acc[i][2] + bv[2]; o0.w = acc[i][3] + bv[3];
        o1.x = acc[i][4] + bv[4]; o1.y = acc[i][5] + bv[5];
        o1.z = acc[i][6] + bv[6]; o1.w = acc[i][7] + bv[7];
        *(float4*)&C[(size_t)r * N + colBase + tx * 8]     = o0;
        *(float4*)&C[(size_t)r * N + colBase + tx * 8 + 4] = o1;
    }
}

// ---------------------------------------------------------------------------
// Flash attention, register-tiled. One block = (b,h,64-query tile).
// 256 threads as 16x16; each thread owns a 4x4 micro-tile of scores/output.
// Both QK^T and PV are 64x64x64 smem GEMMs: 16 FMA / 2 LDS.128.
// Bias folded via a 127-entry per-tile table (depends only on i-j).
// ---------------------------------------------------------------------------
__global__ void __launch_bounds__(256, 2)
flash_attn(const float* __restrict__ q, const float* __restrict__ k,
           const float* __restrict__ v, const float* __restrict__ pb,
           float* __restrict__ out)
{
    const int LD = 68;
    extern __shared__ float sm[];
    float* Qt = sm;             // [d][row]  64x68
    float* Kt = Qt + 64 * LD;   // [d][key]  64x68
    float* Vs = Kt + 64 * LD;   // [key][d]  64x68
    float* Pt = Vs + 64 * LD;   // [key][row] 64x68
    float* sb = Pt + 64 * LD;   // [128] bias table

    int tid = threadIdx.x;
    int tx = tid & 15, ty = tid >> 4;
    int bh = blockIdx.y, b = bh >> 4, h = bh & 15;
    int q0 = blockIdx.x * 64;

    const float c1 = 0.4785533905932738f;   // 1/8 + 64^-0.25
    const float c2 = 0.3535533905932738f;   // 64^-0.25

    // Load Q tile transposed: Qt[d][row]
    #pragma unroll
    for (int i = 0; i < 4; i++) {
        int fi = tid + i * 256;                // 1024 float4s? no: 64x64 floats = 1024 float4
        int r = fi >> 4, dq = (fi & 15) * 4;
        float4 a = *(const float4*)&q[((size_t)(b * S_ + q0 + r)) * D_ + h * HD_ + dq];
        Qt[(dq+0)*LD + r] = a.x; Qt[(dq+1)*LD + r] = a.y;
        Qt[(dq+2)*LD + r] = a.z; Qt[(dq+3)*LD + r] = a.w;
    }

    float m[4] = {-1e30f, -1e30f, -1e30f, -1e30f};
    float l[4] = {0.f, 0.f, 0.f, 0.f};
    float o[4][4] = {};

    for (int kt = 0; kt < S_; kt += 64) {
        // bias table: 127 distinct (i-j) values for this tile pair
        if (tid < 127) {
            int rel = q0 - kt + (tid - 63);
            rel = min(max(rel, -(MAXD - 1)), MAXD - 1) + (MAXD - 1);
            sb[tid] = c2 * __ldg(&pb[rel * H_ + h]);
        }
        // K transposed -> Kt[d][key]; V natural -> Vs[key][d]
        #pragma unroll
        for (int i = 0; i < 4; i++) {
            int fi = tid + i * 256;
            int r = fi >> 4, dq = (fi & 15) * 4;
            size_t g = ((size_t)(b * S_ + kt + r)) * D_ + h * HD_ + dq;
            float4 a = *(const float4*)&k[g];
            Kt[(dq+0)*LD + r] = a.x; Kt[(dq+1)*LD + r] = a.y;
            Kt[(dq+2)*LD + r] = a.z; Kt[(dq+3)*LD + r] = a.w;
            *(float4*)&Vs[r * LD + dq] = *(const float4*)&v[g];
        }
        __syncthreads();

        // --- scores: S = Q @ K^T (64x64x64) ---
        float s[4][4] = {};
        #pragma unroll 8
        for (int kk = 0; kk < 64; kk++) {
            float a[4], bb[4];
            *(float4*)a  = *(const float4*)&Qt[kk * LD + ty * 4];
            *(float4*)bb = *(const float4*)&Kt[kk * LD + tx * 4];
            #pragma unroll
            for (int i = 0; i < 4; i++)
                #pragma unroll
                for (int j = 0; j < 4; j++)
                    s[i][j] += a[i] * bb[j];
        }

        // --- bias + online softmax ---
        #pragma unroll
        for (int i = 0; i < 4; i++) {
            float rmax = -1e30f;
            #pragma unroll
            for (int j = 0; j < 4; j++) {
                int idx = (ty * 4 + i) - (tx * 4 + j) + 63;   // in [0,126]
                s[i][j] = c1 * s[i][j] + sb[idx];
                rmax = fmaxf(rmax, s[i][j]);
            }
            rmax = fmaxf(rmax, __shfl_xor_sync(0xffffffffu, rmax, 1));
            rmax = fmaxf(rmax, __shfl_xor_sync(0xffffffffu, rmax, 2));
            rmax = fmaxf(rmax, __shfl_xor_sync(0xffffffffu, rmax, 4));
            rmax = fmaxf(rmax, __shfl_xor_sync(0xffffffffu, rmax, 8));

            float mn = fmaxf(m[i], rmax);
            float corr = __expf(m[i] - mn);
            m[i] = mn;
            float ls = 0.f;
            #pragma unroll
            for (int j = 0; j < 4; j++) {
                float p = __expf(s[i][j] - mn);
                ls += p;
                Pt[(tx * 4 + j) * LD + ty * 4 + i] = p;   // store P transposed
            }
            ls += __shfl_xor_sync(0xffffffffu, ls, 1);
            ls += __shfl_xor_sync(0xffffffffu, ls, 2);
            ls += __shfl_xor_sync(0xffffffffu, ls, 4);
            ls += __shfl_xor_sync(0xffffffffu, ls, 8);
            l[i] = l[i] * corr + ls;
            #pragma unroll
            for (int j = 0; j < 4; j++) o[i][j] *= corr;
        }
        __syncthreads();   // Pt complete

        // --- O += P @ V (64x64x64) ---
        #pragma unroll 8
        for (int kk = 0; kk < 64; kk++) {
            float a[4], bb[4];
            *(float4*)a  = *(const float4*)&Pt[kk * LD + ty * 4];
            *(float4*)bb = *(const float4*)&Vs[kk * LD + tx * 4];
            #pragma unroll
            for (int i = 0; i < 4; i++)
                #pragma unroll
                for (int j = 0; j < 4; j++)
                    o[i][j] += a[i] * bb[j];
        }
        __syncthreads();   // done with Kt/Vs/Pt/sb before next tile
    }

    #pragma unroll
    for (int i = 0; i < 4; i++) {
        float inv = 1.f / l[i];
        #pragma unroll
        for (int j = 0; j < 4; j++)
            out[((size_t)(b * S_ + q0 + ty * 4 + i)) * D_ + h * HD_ + tx * 4 + j] = o[i][j] * inv;
    }
}

// ---------------------------------------------------------------------------
extern "C" void kernel_launch(void* const* d_in, const int* in_sizes, int n_in,
                              void* d_out, int out_size)
{
    const float* x  = (const float*)d_in[0];
    const float* Wq = (const float*)d_in[1];
    const float* bq = (const float*)d_in[2];
    const float* Wk = (const float*)d_in[3];
    const float* Wv = (const float*)d_in[4];
    const float* bv = (const float*)d_in[5];
    const float* Wo = (const float*)d_in[6];
    const float* bo = (const float*)d_in[7];
    const float* pb = (const float*)d_in[8];
    float* out = (float*)d_out;

    float *q, *k, *v, *attn;
    cudaGetSymbolAddress((void**)&q,    g_q);
    cudaGetSymbolAddress((void**)&k,    g_k);
    cudaGetSymbolAddress((void**)&v,    g_v);
    cudaGetSymbolAddress((void**)&attn, g_attn);

    const int M = B_ * S_;   // 4096
    dim3 gGrid(D_ / 128, M / 128);   // (8, 32)
    dim3 gBlk(256);

    gemm128<true ><<<gGrid, gBlk>>>(x, Wq, bq, q, M, D_, D_);
    gemm128<false><<<gGrid, gBlk>>>(x, Wk, nullptr, k, M, D_, D_);
    gemm128<true ><<<gGrid, gBlk>>>(x, Wv, bv, v, M, D_, D_);

    int smem = (4 * 64 * 68 + 128) * sizeof(float);   // 70144 B
    cudaFuncSetAttribute(flash_attn, cudaFuncAttributeMaxDynamicSharedMemorySize, smem);
    dim3 fGrid(S_ / 64, B_ * H_);   // (32, 32)
    flash_attn<<<fGrid, dim3(256), smem>>>(q, k, v, pb, attn);

    gemm128<true ><<<gGrid, gBlk>>>(attn, Wo, bo, out, M, D_, D_);
}

// round 4
// speedup vs baseline: 4.8634x; 1.3644x over previous
#include <cuda_runtime.h>
#include <cuda_bf16.h>
#include <cstdint>

#define B_ 2
#define S_ 2048
#define D_ 1024
#define H_ 16
#define HD_ 64
#define MAXD 1024

// ---------------- scratch (__device__ globals; no allocs allowed) -----------
__device__ float g_q[B_*S_*D_];
__device__ float g_k[B_*S_*D_];
__device__ float g_v[B_*S_*D_];
__device__ float g_attn[B_*S_*D_];
__device__ __nv_bfloat16 g_xh[B_*S_*D_], g_xl[B_*S_*D_];
__device__ __nv_bfloat16 g_ah[B_*S_*D_], g_al[B_*S_*D_];
__device__ __nv_bfloat16 g_wqh[D_*D_], g_wql[D_*D_];
__device__ __nv_bfloat16 g_wkh[D_*D_], g_wkl[D_*D_];
__device__ __nv_bfloat16 g_wvh[D_*D_], g_wvl[D_*D_];
__device__ __nv_bfloat16 g_woh[D_*D_], g_wol[D_*D_];

// ---------------- PTX helpers (arch-generic: sm_80-era only) ----------------
__device__ __forceinline__ uint32_t s2u(const void* p) {
    uint32_t a;
    asm("{ .reg .u64 t; cvta.to.shared.u64 t, %1; cvt.u32.u64 %0, t; }" : "=r"(a) : "l"(p));
    return a;
}
#define CPA16(d, s) asm volatile("cp.async.cg.shared.global [%0], [%1], 16;" :: "r"(d), "l"(s))
#define CPC()       asm volatile("cp.async.commit_group;" ::: "memory")
#define CPW(n)      asm volatile("cp.async.wait_group %0;" :: "n"(n) : "memory")

__device__ __forceinline__ void ldm_x4(uint32_t* r, uint32_t addr) {
    asm volatile("ldmatrix.sync.aligned.m8n8.x4.shared.b16 {%0,%1,%2,%3}, [%4];"
                 : "=r"(r[0]), "=r"(r[1]), "=r"(r[2]), "=r"(r[3]) : "r"(addr));
}
__device__ __forceinline__ void mma_bf16(float* d, const uint32_t* a, const uint32_t* b) {
    asm volatile("mma.sync.aligned.m16n8k16.row.col.f32.bf16.bf16.f32 "
                 "{%0,%1,%2,%3}, {%4,%5,%6,%7}, {%8,%9}, {%0,%1,%2,%3};"
                 : "+f"(d[0]), "+f"(d[1]), "+f"(d[2]), "+f"(d[3])
                 : "r"(a[0]), "r"(a[1]), "r"(a[2]), "r"(a[3]), "r"(b[0]), "r"(b[1]));
}

// ---------------- fp32 -> (hi,lo) bf16 split --------------------------------
__global__ void cvt_split(const float* __restrict__ x, __nv_bfloat16* __restrict__ h,
                          __nv_bfloat16* __restrict__ l, int n4)
{
    int i = blockIdx.x * blockDim.x + threadIdx.x;
    if (i >= n4) return;
    float4 v = ((const float4*)x)[i];
    float vs[4] = {v.x, v.y, v.z, v.w};
    #pragma unroll
    for (int j = 0; j < 4; j++) {
        __nv_bfloat16 hb = __float2bfloat16(vs[j]);
        h[i*4+j] = hb;
        l[i*4+j] = __float2bfloat16(vs[j] - __bfloat162float(hb));
    }
}

// ---------------- W[K,N] -> Wt[N,K] with hi/lo split -------------------------
__global__ void transpose_split(const float* __restrict__ W,
                                __nv_bfloat16* __restrict__ Th, __nv_bfloat16* __restrict__ Tl)
{
    __shared__ float t[32][33];
    int bx = blockIdx.x * 32;    // n
    int by = blockIdx.y * 32;    // k
    int tx = threadIdx.x, ty = threadIdx.y;
    #pragma unroll
    for (int i = 0; i < 4; i++)
        t[ty + i*8][tx] = W[(size_t)(by + ty + i*8) * D_ + bx + tx];
    __syncthreads();
    #pragma unroll
    for (int i = 0; i < 4; i++) {
        float vv = t[tx][ty + i*8];
        __nv_bfloat16 hb = __float2bfloat16(vv);
        size_t o = (size_t)(bx + ty + i*8) * D_ + by + tx;
        Th[o] = hb;
        Tl[o] = __float2bfloat16(vv - __bfloat162float(hb));
    }
}

// ---------------- mma.sync split-bf16 GEMM: C = A @ B^T (+bias) -------------
// A: [M,1024] K-major hi/lo. B: [N,1024] K-major hi/lo (pre-transposed W).
// CTA 128x128, 8 warps (64x32 each), BK=64, 3-stage cp.async pipeline.
#define NCHUNK 16
#define STAGE_BYTES 65536          // Ah/Al/Bh/Bl tiles, 16 KB each
__global__ void __launch_bounds__(256, 1)
mma_gemm(const __nv_bfloat16* __restrict__ Ah, const __nv_bfloat16* __restrict__ Al,
         const __nv_bfloat16* __restrict__ Bh, const __nv_bfloat16* __restrict__ Bl,
         const float* __restrict__ bias, float* __restrict__ C)
{
    extern __shared__ char smem[];
    uint32_t sb = s2u(smem);     // 1024-aligned (dynamic smem is)

    int tid = threadIdx.x, wid = tid >> 5, lane = tid & 31;
    int wr = wid >> 2, wc = wid & 3;             // warp row (0..1), warp col (0..3)
    int rowBase = blockIdx.y * 128, colBase = blockIdx.x * 128;

    const __nv_bfloat16* bases[4] = {
        Ah + (size_t)rowBase * D_, Al + (size_t)rowBase * D_,
        Bh + (size_t)colBase * D_, Bl + (size_t)colBase * D_ };

    // 128 rows x 128B per tile; granule g swizzled by row&7
    #define LOAD_CHUNK(c_, st_) do { \
        int k0_ = (c_) * 64; \
        uint32_t d0_ = sb + (st_) * STAGE_BYTES; \
        _Pragma("unroll") \
        for (int t_ = 0; t_ < 4; t_++) { \
            const __nv_bfloat16* s_ = bases[t_]; \
            _Pragma("unroll") \
            for (int i_ = 0; i_ < 4; i_++) { \
                int idx_ = tid + i_ * 256; \
                int rr_ = idx_ >> 3, gq_ = idx_ & 7; \
                uint32_t dd_ = d0_ + t_ * 16384 + rr_ * 128 + ((gq_ ^ (rr_ & 7)) << 4); \
                CPA16(dd_, s_ + (size_t)rr_ * D_ + k0_ + gq_ * 8); \
            } \
        } \
        CPC(); \
    } while (0)

    LOAD_CHUNK(0, 0);
    LOAD_CHUNK(1, 1);

    float acc[4][4][4] = {};      // [m-tile][n-tile][4 regs]

    for (int c = 0; c < NCHUNK; c++) {
        if (c < NCHUNK - 1) CPW(1); else CPW(0);
        __syncthreads();
        if (c + 2 < NCHUNK) LOAD_CHUNK(c + 2, (c + 2) % 3);

        uint32_t stg = sb + (c % 3) * STAGE_BYTES;

        #pragma unroll
        for (int ks = 0; ks < 4; ks++) {
            uint32_t a_hi[4][4], a_lo[4][4];
            #pragma unroll
            for (int mi = 0; mi < 4; mi++) {
                int row = wr * 64 + mi * 16 + (lane & 15);
                int kg  = ks * 2 + (lane >> 4);
                uint32_t addr = stg + row * 128 + ((kg ^ (row & 7)) << 4);
                ldm_x4(a_hi[mi], addr);
                ldm_x4(a_lo[mi], addr + 16384);
            }
            uint32_t b_hi[2][4], b_lo[2][4];
            #pragma unroll
            for (int nj = 0; nj < 2; nj++) {
                int rowb = wc * 32 + nj * 16 + (lane & 7) + ((lane & 16) ? 8 : 0);
                int kg   = ks * 2 + ((lane >> 3) & 1);
                uint32_t addr = stg + 32768 + rowb * 128 + ((kg ^ (rowb & 7)) << 4);
                ldm_x4(b_hi[nj], addr);
                ldm_x4(b_lo[nj], addr + 16384);
            }
            #pragma unroll
            for (int mi = 0; mi < 4; mi++)
                #pragma unroll
                for (int ni = 0; ni < 4; ni++) {
                    const uint32_t* bh = &b_hi[ni >> 1][(ni & 1) * 2];
                    const uint32_t* bl = &b_lo[ni >> 1][(ni & 1) * 2];
                    mma_bf16(acc[mi][ni], a_hi[mi], bh);
                    mma_bf16(acc[mi][ni], a_hi[mi], bl);
                    mma_bf16(acc[mi][ni], a_lo[mi], bh);
                }
        }
    }

    // epilogue: fragment (lane/4, 2*(lane%4)) rows +0/+8
    #pragma unroll
    for (int ni = 0; ni < 4; ni++) {
        int col = colBase + wc * 32 + ni * 8 + (lane & 3) * 2;
        float2 bb = bias ? *(const float2*)&bias[col] : make_float2(0.f, 0.f);
        #pragma unroll
        for (int mi = 0; mi < 4; mi++) {
            int row = rowBase + wr * 64 + mi * 16 + (lane >> 2);
            float2 o0 = make_float2(acc[mi][ni][0] + bb.x, acc[mi][ni][1] + bb.y);
            float2 o1 = make_float2(acc[mi][ni][2] + bb.x, acc[mi][ni][3] + bb.y);
            *(float2*)&C[(size_t)row * D_ + col]       = o0;
            *(float2*)&C[(size_t)(row + 8) * D_ + col] = o1;
        }
    }
}

// ---------------------------------------------------------------------------
// Flash attention (unchanged): register-tiled SIMT.
// ---------------------------------------------------------------------------
__global__ void __launch_bounds__(256, 2)
flash_attn(const float* __restrict__ q, const float* __restrict__ k,
           const float* __restrict__ v, const float* __restrict__ pb,
           float* __restrict__ out)
{
    const int LD = 68;
    extern __shared__ float sm[];
    float* Qt = sm;
    float* Kt = Qt + 64 * LD;
    float* Vs = Kt + 64 * LD;
    float* Pt = Vs + 64 * LD;
    float* sb = Pt + 64 * LD;

    int tid = threadIdx.x;
    int tx = tid & 15, ty = tid >> 4;
    int bh = blockIdx.y, b = bh >> 4, h = bh & 15;
    int q0 = blockIdx.x * 64;

    const float c1 = 0.4785533905932738f;
    const float c2 = 0.3535533905932738f;

    #pragma unroll
    for (int i = 0; i < 4; i++) {
        int fi = tid + i * 256;
        int r = fi >> 4, dq = (fi & 15) * 4;
        float4 a = *(const float4*)&q[((size_t)(b * S_ + q0 + r)) * D_ + h * HD_ + dq];
        Qt[(dq+0)*LD + r] = a.x; Qt[(dq+1)*LD + r] = a.y;
        Qt[(dq+2)*LD + r] = a.z; Qt[(dq+3)*LD + r] = a.w;
    }

    float m[4] = {-1e30f, -1e30f, -1e30f, -1e30f};
    float l[4] = {0.f, 0.f, 0.f, 0.f};
    float o[4][4] = {};

    for (int kt = 0; kt < S_; kt += 64) {
        if (tid < 127) {
            int rel = q0 - kt + (tid - 63);
            rel = min(max(rel, -(MAXD - 1)), MAXD - 1) + (MAXD - 1);
            sb[tid] = c2 * __ldg(&pb[rel * H_ + h]);
        }
        #pragma unroll
        for (int i = 0; i < 4; i++) {
            int fi = tid + i * 256;
            int r = fi >> 4, dq = (fi & 15) * 4;
            size_t g = ((size_t)(b * S_ + kt + r)) * D_ + h * HD_ + dq;
            float4 a = *(const float4*)&k[g];
            Kt[(dq+0)*LD + r] = a.x; Kt[(dq+1)*LD + r] = a.y;
            Kt[(dq+2)*LD + r] = a.z; Kt[(dq+3)*LD + r] = a.w;
            *(float4*)&Vs[r * LD + dq] = *(const float4*)&v[g];
        }
        __syncthreads();

        float s[4][4] = {};
        #pragma unroll 8
        for (int kk = 0; kk < 64; kk++) {
            float a[4], bb[4];
            *(float4*)a  = *(const float4*)&Qt[kk * LD + ty * 4];
            *(float4*)bb = *(const float4*)&Kt[kk * LD + tx * 4];
            #pragma unroll
            for (int i = 0; i < 4; i++)
                #pragma unroll
                for (int j = 0; j < 4; j++)
                    s[i][j] += a[i] * bb[j];
        }

        #pragma unroll
        for (int i = 0; i < 4; i++) {
            float rmax = -1e30f;
            #pragma unroll
            for (int j = 0; j < 4; j++) {
                int idx = (ty * 4 + i) - (tx * 4 + j) + 63;
                s[i][j] = c1 * s[i][j] + sb[idx];
                rmax = fmaxf(rmax, s[i][j]);
            }
            rmax = fmaxf(rmax, __shfl_xor_sync(0xffffffffu, rmax, 1));
            rmax = fmaxf(rmax, __shfl_xor_sync(0xffffffffu, rmax, 2));
            rmax = fmaxf(rmax, __shfl_xor_sync(0xffffffffu, rmax, 4));
            rmax = fmaxf(rmax, __shfl_xor_sync(0xffffffffu, rmax, 8));

            float mn = fmaxf(m[i], rmax);
            float corr = __expf(m[i] - mn);
            m[i] = mn;
            float ls = 0.f;
            #pragma unroll
            for (int j = 0; j < 4; j++) {
                float p = __expf(s[i][j] - mn);
                ls += p;
                Pt[(tx * 4 + j) * LD + ty * 4 + i] = p;
            }
            ls += __shfl_xor_sync(0xffffffffu, ls, 1);
            ls += __shfl_xor_sync(0xffffffffu, ls, 2);
            ls += __shfl_xor_sync(0xffffffffu, ls, 4);
            ls += __shfl_xor_sync(0xffffffffu, ls, 8);
            l[i] = l[i] * corr + ls;
            #pragma unroll
            for (int j = 0; j < 4; j++) o[i][j] *= corr;
        }
        __syncthreads();

        #pragma unroll 8
        for (int kk = 0; kk < 64; kk++) {
            float a[4], bb[4];
            *(float4*)a  = *(const float4*)&Pt[kk * LD + ty * 4];
            *(float4*)bb = *(const float4*)&Vs[kk * LD + tx * 4];
            #pragma unroll
            for (int i = 0; i < 4; i++)
                #pragma unroll
                for (int j = 0; j < 4; j++)
                    o[i][j] += a[i] * bb[j];
        }
        __syncthreads();
    }

    #pragma unroll
    for (int i = 0; i < 4; i++) {
        float inv = 1.f / l[i];
        #pragma unroll
        for (int j = 0; j < 4; j++)
            out[((size_t)(b * S_ + q0 + ty * 4 + i)) * D_ + h * HD_ + tx * 4 + j] = o[i][j] * inv;
    }
}

// ---------------------------------------------------------------------------
extern "C" void kernel_launch(void* const* d_in, const int* in_sizes, int n_in,
                              void* d_out, int out_size)
{
    const float* x  = (const float*)d_in[0];
    const float* Wq = (const float*)d_in[1];
    const float* bq = (const float*)d_in[2];
    const float* Wk = (const float*)d_in[3];
    const float* Wv = (const float*)d_in[4];
    const float* bv = (const float*)d_in[5];
    const float* Wo = (const float*)d_in[6];
    const float* bo = (const float*)d_in[7];
    const float* pb = (const float*)d_in[8];
    float* out = (float*)d_out;

    float *q, *k, *v, *attn;
    cudaGetSymbolAddress((void**)&q, g_q);
    cudaGetSymbolAddress((void**)&k, g_k);
    cudaGetSymbolAddress((void**)&v, g_v);
    cudaGetSymbolAddress((void**)&attn, g_attn);
    __nv_bfloat16 *xh, *xl, *ah, *al, *wqh, *wql, *wkh, *wkl, *wvh, *wvl, *woh, *wol;
    cudaGetSymbolAddress((void**)&xh, g_xh);   cudaGetSymbolAddress((void**)&xl, g_xl);
    cudaGetSymbolAddress((void**)&ah, g_ah);   cudaGetSymbolAddress((void**)&al, g_al);
    cudaGetSymbolAddress((void**)&wqh, g_wqh); cudaGetSymbolAddress((void**)&wql, g_wql);
    cudaGetSymbolAddress((void**)&wkh, g_wkh); cudaGetSymbolAddress((void**)&wkl, g_wkl);
    cudaGetSymbolAddress((void**)&wvh, g_wvh); cudaGetSymbolAddress((void**)&wvl, g_wvl);
    cudaGetSymbolAddress((void**)&woh, g_woh); cudaGetSymbolAddress((void**)&wol, g_wol);

    const int M = B_ * S_;                 // 4096
    const int NELEM4 = M * D_ / 4;

    cvt_split<<<NELEM4 / 256, 256>>>(x, xh, xl, NELEM4);
    dim3 tGrid(D_ / 32, D_ / 32), tBlk(32, 8);
    transpose_split<<<tGrid, tBlk>>>(Wq, wqh, wql);
    transpose_split<<<tGrid, tBlk>>>(Wk, wkh, wkl);
    transpose_split<<<tGrid, tBlk>>>(Wv, wvh, wvl);
    transpose_split<<<tGrid, tBlk>>>(Wo, woh, wol);

    int gsmem = 3 * STAGE_BYTES;   // 196608 B
    cudaFuncSetAttribute(mma_gemm, cudaFuncAttributeMaxDynamicSharedMemorySize, gsmem);
    dim3 mGrid(D_ / 128, M / 128);              // (8, 32)

    mma_gemm<<<mGrid, 256, gsmem>>>(xh, xl, wqh, wql, bq, q);
    mma_gemm<<<mGrid, 256, gsmem>>>(xh, xl, wkh, wkl, nullptr, k);
    mma_gemm<<<mGrid, 256, gsmem>>>(xh, xl, wvh, wvl, bv, v);

    int fsmem = (4 * 64 * 68 + 128) * sizeof(float);
    cudaFuncSetAttribute(flash_attn, cudaFuncAttributeMaxDynamicSharedMemorySize, fsmem);
    dim3 fGrid(S_ / 64, B_ * H_);
    flash_attn<<<fGrid, dim3(256), fsmem>>>(q, k, v, pb, attn);

    cvt_split<<<NELEM4 / 256, 256>>>(attn, ah, al, NELEM4);
    mma_gemm<<<mGrid, 256, gsmem>>>(ah, al, woh, wol, bo, out);
}

// round 5
// speedup vs baseline: 11.2882x; 2.3210x over previous
#include <cuda_runtime.h>
#include <cuda_bf16.h>
#include <cstdint>

#define B_ 2
#define S_ 2048
#define D_ 1024
#define H_ 16
#define HD_ 64
#define MAXD 1024

typedef __nv_bfloat16 bf16;
typedef __nv_bfloat162 bf162;

// ---------------- scratch (__device__ globals; no allocs allowed) -----------
__device__ bf16 g_xh[B_*S_*D_], g_xl[B_*S_*D_];
__device__ bf16 g_qh[B_*S_*D_], g_ql[B_*S_*D_];
__device__ bf16 g_kh[B_*S_*D_], g_kl[B_*S_*D_];
__device__ bf16 g_vh[B_*S_*D_], g_vl[B_*S_*D_];
__device__ bf16 g_ah[B_*S_*D_], g_al[B_*S_*D_];
__device__ bf16 g_wqh[D_*D_], g_wql[D_*D_];
__device__ bf16 g_wkh[D_*D_], g_wkl[D_*D_];
__device__ bf16 g_wvh[D_*D_], g_wvl[D_*D_];
__device__ bf16 g_woh[D_*D_], g_wol[D_*D_];

// ---------------- PTX helpers (arch-generic sm_80-era only) -----------------
__device__ __forceinline__ uint32_t s2u(const void* p) {
    uint32_t a;
    asm("{ .reg .u64 t; cvta.to.shared.u64 t, %1; cvt.u32.u64 %0, t; }" : "=r"(a) : "l"(p));
    return a;
}
#define CPA16(d, s) asm volatile("cp.async.cg.shared.global [%0], [%1], 16;" :: "r"(d), "l"(s))
#define CPC()       asm volatile("cp.async.commit_group;" ::: "memory")
#define CPW(n)      asm volatile("cp.async.wait_group %0;" :: "n"(n) : "memory")

__device__ __forceinline__ void ldm_x4(uint32_t* r, uint32_t addr) {
    asm volatile("ldmatrix.sync.aligned.m8n8.x4.shared.b16 {%0,%1,%2,%3}, [%4];"
                 : "=r"(r[0]), "=r"(r[1]), "=r"(r[2]), "=r"(r[3]) : "r"(addr));
}
__device__ __forceinline__ void ldm_x4_t(uint32_t* r, uint32_t addr) {
    asm volatile("ldmatrix.sync.aligned.m8n8.x4.trans.shared.b16 {%0,%1,%2,%3}, [%4];"
                 : "=r"(r[0]), "=r"(r[1]), "=r"(r[2]), "=r"(r[3]) : "r"(addr));
}
__device__ __forceinline__ void mma_bf16(float* d, const uint32_t* a, const uint32_t* b) {
    asm volatile("mma.sync.aligned.m16n8k16.row.col.f32.bf16.bf16.f32 "
                 "{%0,%1,%2,%3}, {%4,%5,%6,%7}, {%8,%9}, {%0,%1,%2,%3};"
                 : "+f"(d[0]), "+f"(d[1]), "+f"(d[2]), "+f"(d[3])
                 : "r"(a[0]), "r"(a[1]), "r"(a[2]), "r"(a[3]), "r"(b[0]), "r"(b[1]));
}
__device__ __forceinline__ void split2(float v0, float v1, uint32_t& hi, uint32_t& lo) {
    bf162 hb = __float22bfloat162_rn(make_float2(v0, v1));
    float2 hf = __bfloat1622float2(hb);
    bf162 lb = __float22bfloat162_rn(make_float2(v0 - hf.x, v1 - hf.y));
    hi = *(uint32_t*)&hb;
    lo = *(uint32_t*)&lb;
}

// ---------------- fp32 -> (hi,lo) bf16 split --------------------------------
__global__ void cvt_split(const float* __restrict__ x, bf16* __restrict__ h,
                          bf16* __restrict__ l, int n4)
{
    int i = blockIdx.x * blockDim.x + threadIdx.x;
    if (i >= n4) return;
    float4 v = ((const float4*)x)[i];
    float vs[4] = {v.x, v.y, v.z, v.w};
    #pragma unroll
    for (int j = 0; j < 4; j++) {
        bf16 hb = __float2bfloat16(vs[j]);
        h[i*4+j] = hb;
        l[i*4+j] = __float2bfloat16(vs[j] - __bfloat162float(hb));
    }
}

// ---------------- W[K,N] -> Wt[N,K] with hi/lo split -------------------------
__global__ void transpose_split(const float* __restrict__ W,
                                bf16* __restrict__ Th, bf16* __restrict__ Tl)
{
    __shared__ float t[32][33];
    int bx = blockIdx.x * 32, by = blockIdx.y * 32;
    int tx = threadIdx.x, ty = threadIdx.y;
    #pragma unroll
    for (int i = 0; i < 4; i++)
        t[ty + i*8][tx] = W[(size_t)(by + ty + i*8) * D_ + bx + tx];
    __syncthreads();
    #pragma unroll
    for (int i = 0; i < 4; i++) {
        float vv = t[tx][ty + i*8];
        bf16 hb = __float2bfloat16(vv);
        size_t o = (size_t)(bx + ty + i*8) * D_ + by + tx;
        Th[o] = hb;
        Tl[o] = __float2bfloat16(vv - __bfloat162float(hb));
    }
}

// ---------------- mma.sync split-bf16 GEMM: C = A @ B^T (+bias) -------------
// Output: fp32 (Cf) or split bf16 (Ch/Cl).
#define NCHUNK 16
#define STAGE_BYTES 65536
__global__ void __launch_bounds__(256, 1)
mma_gemm(const bf16* __restrict__ Ah, const bf16* __restrict__ Al,
         const bf16* __restrict__ Bh, const bf16* __restrict__ Bl,
         const float* __restrict__ bias, float* __restrict__ Cf,
         bf16* __restrict__ Ch, bf16* __restrict__ Cl)
{
    extern __shared__ char smem[];
    uint32_t sb = s2u(smem);

    int tid = threadIdx.x, wid = tid >> 5, lane = tid & 31;
    int wr = wid >> 2, wc = wid & 3;
    int rowBase = blockIdx.y * 128, colBase = blockIdx.x * 128;

    const bf16* bases[4] = {
        Ah + (size_t)rowBase * D_, Al + (size_t)rowBase * D_,
        Bh + (size_t)colBase * D_, Bl + (size_t)colBase * D_ };

    #define LOAD_CHUNK(c_, st_) do { \
        int k0_ = (c_) * 64; \
        uint32_t d0_ = sb + (st_) * STAGE_BYTES; \
        _Pragma("unroll") \
        for (int t_ = 0; t_ < 4; t_++) { \
            const bf16* s_ = bases[t_]; \
            _Pragma("unroll") \
            for (int i_ = 0; i_ < 4; i_++) { \
                int idx_ = tid + i_ * 256; \
                int rr_ = idx_ >> 3, gq_ = idx_ & 7; \
                uint32_t dd_ = d0_ + t_ * 16384 + rr_ * 128 + ((gq_ ^ (rr_ & 7)) << 4); \
                CPA16(dd_, s_ + (size_t)rr_ * D_ + k0_ + gq_ * 8); \
            } \
        } \
        CPC(); \
    } while (0)

    LOAD_CHUNK(0, 0);
    LOAD_CHUNK(1, 1);

    float acc[4][4][4] = {};

    for (int c = 0; c < NCHUNK; c++) {
        if (c < NCHUNK - 1) CPW(1); else CPW(0);
        __syncthreads();
        if (c + 2 < NCHUNK) LOAD_CHUNK(c + 2, (c + 2) % 3);

        uint32_t stg = sb + (c % 3) * STAGE_BYTES;

        #pragma unroll
        for (int ks = 0; ks < 4; ks++) {
            uint32_t a_hi[4][4], a_lo[4][4];
            #pragma unroll
            for (int mi = 0; mi < 4; mi++) {
                int row = wr * 64 + mi * 16 + (lane & 15);
                int kg  = ks * 2 + (lane >> 4);
                uint32_t addr = stg + row * 128 + ((kg ^ (row & 7)) << 4);
                ldm_x4(a_hi[mi], addr);
                ldm_x4(a_lo[mi], addr + 16384);
            }
            uint32_t b_hi[2][4], b_lo[2][4];
            #pragma unroll
            for (int nj = 0; nj < 2; nj++) {
                int rowb = wc * 32 + nj * 16 + (lane & 7) + ((lane & 16) ? 8 : 0);
                int kg   = ks * 2 + ((lane >> 3) & 1);
                uint32_t addr = stg + 32768 + rowb * 128 + ((kg ^ (rowb & 7)) << 4);
                ldm_x4(b_hi[nj], addr);
                ldm_x4(b_lo[nj], addr + 16384);
            }
            #pragma unroll
            for (int mi = 0; mi < 4; mi++)
                #pragma unroll
                for (int ni = 0; ni < 4; ni++) {
                    const uint32_t* bh = &b_hi[ni >> 1][(ni & 1) * 2];
                    const uint32_t* bl = &b_lo[ni >> 1][(ni & 1) * 2];
                    mma_bf16(acc[mi][ni], a_hi[mi], bh);
                    mma_bf16(acc[mi][ni], a_hi[mi], bl);
                    mma_bf16(acc[mi][ni], a_lo[mi], bh);
                }
        }
    }

    #pragma unroll
    for (int ni = 0; ni < 4; ni++) {
        int col = colBase + wc * 32 + ni * 8 + (lane & 3) * 2;
        float2 bb = bias ? *(const float2*)&bias[col] : make_float2(0.f, 0.f);
        #pragma unroll
        for (int mi = 0; mi < 4; mi++) {
            int row = rowBase + wr * 64 + mi * 16 + (lane >> 2);
            float v00 = acc[mi][ni][0] + bb.x, v01 = acc[mi][ni][1] + bb.y;
            float v10 = acc[mi][ni][2] + bb.x, v11 = acc[mi][ni][3] + bb.y;
            if (Cf) {
                *(float2*)&Cf[(size_t)row * D_ + col]       = make_float2(v00, v01);
                *(float2*)&Cf[(size_t)(row + 8) * D_ + col] = make_float2(v10, v11);
            } else {
                uint32_t h0, l0, h1, l1;
                split2(v00, v01, h0, l0);
                split2(v10, v11, h1, l1);
                *(uint32_t*)&Ch[(size_t)row * D_ + col]       = h0;
                *(uint32_t*)&Cl[(size_t)row * D_ + col]       = l0;
                *(uint32_t*)&Ch[(size_t)(row + 8) * D_ + col] = h1;
                *(uint32_t*)&Cl[(size_t)(row + 8) * D_ + col] = l1;
            }
        }
    }
}

// ---------------------------------------------------------------------------
// Tensor-core flash attention. CTA = 128 q-rows x one (b,h). 8 warps: each
// owns m16 x n64. K/V tiles of 64 keys (hi/lo), 3-stage cp.async pipeline.
// S = QhKh+QhKl+QlKh; O = PhVh+PlVh+PhVl; exp2-domain softmax; bias via
// double-buffered 191-entry table. Output written as split bf16 (Ah/Al).
// ---------------------------------------------------------------------------
#define FA_QH   0
#define FA_QL   16384
#define FA_STG  32768          // 3 stages x 32768 (KH,KL,VH,VL 8KB each)
#define FA_TB   131072         // float[2][192]
#define FA_SMEM (131072 + 2*192*4)
#define NKT     (S_/64)

__global__ void __launch_bounds__(256, 1)
flash_mma(const bf16* __restrict__ qh, const bf16* __restrict__ ql,
          const bf16* __restrict__ kh, const bf16* __restrict__ kl,
          const bf16* __restrict__ vh, const bf16* __restrict__ vl,
          const float* __restrict__ pb,
          bf16* __restrict__ oh, bf16* __restrict__ ol)
{
    extern __shared__ char smem[];
    uint32_t sbase = s2u(smem);
    float* tb = (float*)(smem + FA_TB);

    int tid = threadIdx.x, w = tid >> 5, lane = tid & 31;
    int bh = blockIdx.y, b = bh >> 4, h = bh & 15;
    int q0 = blockIdx.x * 128;

    const float LOG2E = 1.4426950408889634f;
    const float c1L = 0.4785533905932738f * LOG2E;
    const float c2L = 0.3535533905932738f * LOG2E;

    size_t toff = (size_t)(b * S_) * D_ + h * HD_;
    const bf16* kvp[4] = {kh + toff, kl + toff, vh + toff, vl + toff};
    const bf16* qp[2]  = {qh + toff, ql + toff};

    // ---- Q tile (128 rows x 64d, hi/lo) cp.async ----
    #pragma unroll
    for (int t = 0; t < 2; t++) {
        #pragma unroll
        for (int i = 0; i < 4; i++) {
            int idx = tid + i * 256;          // 1024 granules
            int r = idx >> 3, g = idx & 7;
            uint32_t dd = sbase + t * 16384 + r * 128 + ((g ^ (r & 7)) << 4);
            CPA16(dd, qp[t] + (size_t)(q0 + r) * D_ + g * 8);
        }
    }
    #define LOAD_KV(c_, st_) do { \
        int kt_ = (c_) * 64; \
        uint32_t d0_ = sbase + FA_STG + (st_) * 32768; \
        _Pragma("unroll") \
        for (int t_ = 0; t_ < 4; t_++) { \
            _Pragma("unroll") \
            for (int i_ = 0; i_ < 2; i_++) { \
                int idx_ = tid + i_ * 256;      /* 512 granules */ \
                int r_ = idx_ >> 3, g_ = idx_ & 7; \
                uint32_t dd_ = d0_ + t_ * 8192 + r_ * 128 + ((g_ ^ (r_ & 7)) << 4); \
                CPA16(dd_, kvp[t_] + (size_t)(kt_ + r_) * D_ + g_ * 8); \
            } \
        } \
        CPC(); \
    } while (0)

    LOAD_KV(0, 0);           // group 0 = Q + stage0
    LOAD_KV(1, 1);           // group 1 = stage1

    // bias table for tile 0 (buffer 0)
    if (tid < 192) {
        int rel = q0 - 0 + (tid - 63);
        rel = min(max(rel, -(MAXD - 1)), MAXD - 1) + (MAXD - 1);
        tb[tid] = c2L * __ldg(&pb[rel * H_ + h]);
    }

    uint32_t qa_h[4][4], qa_l[4][4];
    float o[8][4] = {};
    float m0 = -1e30f, m1 = -1e30f, l0 = 0.f, l1 = 0.f;

    for (int c = 0; c < NKT; c++) {
        if (c < NKT - 1) CPW(1); else CPW(0);
        __syncthreads();

        if (c == 0) {        // Q fragments once, kept in registers
            #pragma unroll
            for (int ks = 0; ks < 4; ks++) {
                int row = w * 16 + (lane & 15);
                int kg  = ks * 2 + (lane >> 4);
                uint32_t addr = sbase + row * 128 + ((kg ^ (row & 7)) << 4);
                ldm_x4(qa_h[ks], addr);
                ldm_x4(qa_l[ks], addr + 16384);
            }
        }
        if (c + 2 < NKT) LOAD_KV(c + 2, (c + 2) % 3);
        if (c + 1 < NKT && tid < 192) {
            int rel = q0 - (c + 1) * 64 + (tid - 63);
            rel = min(max(rel, -(MAXD - 1)), MAXD - 1) + (MAXD - 1);
            tb[((c + 1) & 1) * 192 + tid] = c2L * __ldg(&pb[rel * H_ + h]);
        }

        uint32_t stg = sbase + FA_STG + (c % 3) * 32768;
        const float* tbc = tb + (c & 1) * 192;

        // ---- S = Q K^T (3 split passes) ----
        float s[8][4] = {};
        #pragma unroll
        for (int ks = 0; ks < 4; ks++) {
            uint32_t bK_h[4][4], bK_l[4][4];
            #pragma unroll
            for (int nj = 0; nj < 4; nj++) {
                int rowb = nj * 16 + (lane & 7) + ((lane & 16) ? 8 : 0);
                int kg   = ks * 2 + ((lane >> 3) & 1);
                uint32_t addr = stg + rowb * 128 + ((kg ^ (rowb & 7)) << 4);
                ldm_x4(bK_h[nj], addr);
                ldm_x4(bK_l[nj], addr + 8192);
            }
            #pragma unroll
            for (int ni = 0; ni < 8; ni++) {
                const uint32_t* bh2 = &bK_h[ni >> 1][(ni & 1) * 2];
                const uint32_t* bl2 = &bK_l[ni >> 1][(ni & 1) * 2];
                mma_bf16(s[ni], qa_h[ks], bh2);
                mma_bf16(s[ni], qa_h[ks], bl2);
                mma_bf16(s[ni], qa_l[ks], bh2);
            }
        }

        // ---- bias + online softmax (exp2 domain) ----
        int i0 = w * 16 + (lane >> 2);
        int jb = 2 * (lane & 3);
        float t0 = -1e30f, t1 = -1e30f;
        #pragma unroll
        for (int ni = 0; ni < 8; ni++) {
            int tix = i0 - (8 * ni + jb) + 63;
            s[ni][0] = fmaf(c1L, s[ni][0], tbc[tix]);
            s[ni][1] = fmaf(c1L, s[ni][1], tbc[tix - 1]);
            s[ni][2] = fmaf(c1L, s[ni][2], tbc[tix + 8]);
            s[ni][3] = fmaf(c1L, s[ni][3], tbc[tix + 7]);
            t0 = fmaxf(t0, fmaxf(s[ni][0], s[ni][1]));
            t1 = fmaxf(t1, fmaxf(s[ni][2], s[ni][3]));
        }
        t0 = fmaxf(t0, __shfl_xor_sync(0xffffffffu, t0, 1));
        t0 = fmaxf(t0, __shfl_xor_sync(0xffffffffu, t0, 2));
        t1 = fmaxf(t1, __shfl_xor_sync(0xffffffffu, t1, 1));
        t1 = fmaxf(t1, __shfl_xor_sync(0xffffffffu, t1, 2));
        float m0n = fmaxf(m0, t0), m1n = fmaxf(m1, t1);
        float cr0 = exp2f(m0 - m0n), cr1 = exp2f(m1 - m1n);
        m0 = m0n; m1 = m1n;

        float ls0 = 0.f, ls1 = 0.f;
        #pragma unroll
        for (int ni = 0; ni < 8; ni++) {
            s[ni][0] = exp2f(s[ni][0] - m0);
            s[ni][1] = exp2f(s[ni][1] - m0);
            s[ni][2] = exp2f(s[ni][2] - m1);
            s[ni][3] = exp2f(s[ni][3] - m1);
            ls0 += s[ni][0] + s[ni][1];
            ls1 += s[ni][2] + s[ni][3];
            o[ni][0] *= cr0; o[ni][1] *= cr0;
            o[ni][2] *= cr1; o[ni][3] *= cr1;
        }
        l0 = l0 * cr0 + ls0;
        l1 = l1 * cr1 + ls1;

        // ---- O += P V (3 split passes) ----
        #pragma unroll
        for (int t = 0; t < 4; t++) {
            uint32_t a_h[4], a_l[4];
            split2(s[2*t][0],   s[2*t][1],   a_h[0], a_l[0]);
            split2(s[2*t][2],   s[2*t][3],   a_h[1], a_l[1]);
            split2(s[2*t+1][0], s[2*t+1][1], a_h[2], a_l[2]);
            split2(s[2*t+1][2], s[2*t+1][3], a_h[3], a_l[3]);

            uint32_t bV_h[4][4], bV_l[4][4];
            #pragma unroll
            for (int vj = 0; vj < 4; vj++) {
                int rowv = t * 16 + (lane & 7) + ((lane & 8) ? 8 : 0);
                int gq   = 2 * vj + ((lane >> 4) & 1);
                uint32_t addr = stg + 16384 + rowv * 128 + ((gq ^ (rowv & 7)) << 4);
                ldm_x4_t(bV_h[vj], addr);
                ldm_x4_t(bV_l[vj], addr + 8192);
            }
            #pragma unroll
            for (int ni = 0; ni < 8; ni++) {
                const uint32_t* bh2 = &bV_h[ni >> 1][(ni & 1) * 2];
                const uint32_t* bl2 = &bV_l[ni >> 1][(ni & 1) * 2];
                mma_bf16(o[ni], a_h, bh2);
                mma_bf16(o[ni], a_l, bh2);
                mma_bf16(o[ni], a_h, bl2);
            }
        }
    }

    l0 += __shfl_xor_sync(0xffffffffu, l0, 1);
    l0 += __shfl_xor_sync(0xffffffffu, l0, 2);
    l1 += __shfl_xor_sync(0xffffffffu, l1, 1);
    l1 += __shfl_xor_sync(0xffffffffu, l1, 2);
    float inv0 = 1.f / l0, inv1 = 1.f / l1;

    int row0 = b * S_ + q0 + w * 16 + (lane >> 2);
    #pragma unroll
    for (int ni = 0; ni < 8; ni++) {
        int col = h * HD_ + 8 * ni + 2 * (lane & 3);
        uint32_t h0, lo0, h1, lo1;
        split2(o[ni][0] * inv0, o[ni][1] * inv0, h0, lo0);
        split2(o[ni][2] * inv1, o[ni][3] * inv1, h1, lo1);
        *(uint32_t*)&oh[(size_t)row0 * D_ + col]       = h0;
        *(uint32_t*)&ol[(size_t)row0 * D_ + col]       = lo0;
        *(uint32_t*)&oh[(size_t)(row0 + 8) * D_ + col] = h1;
        *(uint32_t*)&ol[(size_t)(row0 + 8) * D_ + col] = lo1;
    }
}

// ---------------------------------------------------------------------------
extern "C" void kernel_launch(void* const* d_in, const int* in_sizes, int n_in,
                              void* d_out, int out_size)
{
    const float* x  = (const float*)d_in[0];
    const float* Wq = (const float*)d_in[1];
    const float* bq = (const float*)d_in[2];
    const float* Wk = (const float*)d_in[3];
    const float* Wv = (const float*)d_in[4];
    const float* bv = (const float*)d_in[5];
    const float* Wo = (const float*)d_in[6];
    const float* bo = (const float*)d_in[7];
    const float* pb = (const float*)d_in[8];
    float* out = (float*)d_out;

    bf16 *xh, *xl, *qh, *ql, *kh, *kl, *vh, *vl, *ah, *al;
    bf16 *wqh, *wql, *wkh, *wkl, *wvh, *wvl, *woh, *wol;
    cudaGetSymbolAddress((void**)&xh, g_xh);   cudaGetSymbolAddress((void**)&xl, g_xl);
    cudaGetSymbolAddress((void**)&qh, g_qh);   cudaGetSymbolAddress((void**)&ql, g_ql);
    cudaGetSymbolAddress((void**)&kh, g_kh);   cudaGetSymbolAddress((void**)&kl, g_kl);
    cudaGetSymbolAddress((void**)&vh, g_vh);   cudaGetSymbolAddress((void**)&vl, g_vl);
    cudaGetSymbolAddress((void**)&ah, g_ah);   cudaGetSymbolAddress((void**)&al, g_al);
    cudaGetSymbolAddress((void**)&wqh, g_wqh); cudaGetSymbolAddress((void**)&wql, g_wql);
    cudaGetSymbolAddress((void**)&wkh, g_wkh); cudaGetSymbolAddress((void**)&wkl, g_wkl);
    cudaGetSymbolAddress((void**)&wvh, g_wvh); cudaGetSymbolAddress((void**)&wvl, g_wvl);
    cudaGetSymbolAddress((void**)&woh, g_woh); cudaGetSymbolAddress((void**)&wol, g_wol);

    const int M = B_ * S_;
    const int NELEM4 = M * D_ / 4;

    cvt_split<<<NELEM4 / 256, 256>>>(x, xh, xl, NELEM4);
    dim3 tGrid(D_ / 32, D_ / 32), tBlk(32, 8);
    transpose_split<<<tGrid, tBlk>>>(Wq, wqh, wql);
    transpose_split<<<tGrid, tBlk>>>(Wk, wkh, wkl);
    transpose_split<<<tGrid, tBlk>>>(Wv, wvh, wvl);
    transpose_split<<<tGrid, tBlk>>>(Wo, woh, wol);

    int gsmem = 3 * STAGE_BYTES;
    cudaFuncSetAttribute(mma_gemm, cudaFuncAttributeMaxDynamicSharedMemorySize, gsmem);
    dim3 mGrid(D_ / 128, M / 128);

    mma_gemm<<<mGrid, 256, gsmem>>>(xh, xl, wqh, wql, bq, nullptr, qh, ql);
    mma_gemm<<<mGrid, 256, gsmem>>>(xh, xl, wkh, wkl, nullptr, nullptr, kh, kl);
    mma_gemm<<<mGrid, 256, gsmem>>>(xh, xl, wvh, wvl, bv, nullptr, vh, vl);

    cudaFuncSetAttribute(flash_mma, cudaFuncAttributeMaxDynamicSharedMemorySize, FA_SMEM);
    dim3 fGrid(S_ / 128, B_ * H_);   // (16, 32)
    flash_mma<<<fGrid, 256, FA_SMEM>>>(qh, ql, kh, kl, vh, vl, pb, ah, al);

    mma_gemm<<<mGrid, 256, gsmem>>>(ah, al, woh, wol, bo, out, nullptr, nullptr);
}

// round 6
// speedup vs baseline: 12.0541x; 1.0679x over previous
#include <cuda_runtime.h>
#include <cuda_bf16.h>
#include <cstdint>

#define B_ 2
#define S_ 2048
#define D_ 1024
#define H_ 16
#define HD_ 64
#define MAXD 1024

typedef __nv_bfloat16 bf16;
typedef __nv_bfloat162 bf162;

// ---------------- scratch (__device__ globals; no allocs allowed) -----------
__device__ bf16 g_xh[B_*S_*D_], g_xl[B_*S_*D_];
__device__ bf16 g_qh[B_*S_*D_], g_ql[B_*S_*D_];
__device__ bf16 g_kh[B_*S_*D_], g_kl[B_*S_*D_];
__device__ bf16 g_vh[B_*S_*D_], g_vl[B_*S_*D_];
__device__ bf16 g_ah[B_*S_*D_], g_al[B_*S_*D_];
__device__ bf16 g_wqh[D_*D_], g_wql[D_*D_];
__device__ bf16 g_wkh[D_*D_], g_wkl[D_*D_];
__device__ bf16 g_wvh[D_*D_], g_wvl[D_*D_];
__device__ bf16 g_woh[D_*D_], g_wol[D_*D_];

// ---------------- PTX helpers (arch-generic sm_80-era only) -----------------
__device__ __forceinline__ uint32_t s2u(const void* p) {
    uint32_t a;
    asm("{ .reg .u64 t; cvta.to.shared.u64 t, %1; cvt.u32.u64 %0, t; }" : "=r"(a) : "l"(p));
    return a;
}
#define CPA16(d, s) asm volatile("cp.async.cg.shared.global [%0], [%1], 16;" :: "r"(d), "l"(s))
#define CPC()       asm volatile("cp.async.commit_group;" ::: "memory")
#define CPW(n)      asm volatile("cp.async.wait_group %0;" :: "n"(n) : "memory")

__device__ __forceinline__ void ldm_x4(uint32_t* r, uint32_t addr) {
    asm volatile("ldmatrix.sync.aligned.m8n8.x4.shared.b16 {%0,%1,%2,%3}, [%4];"
                 : "=r"(r[0]), "=r"(r[1]), "=r"(r[2]), "=r"(r[3]) : "r"(addr));
}
__device__ __forceinline__ void ldm_x4_t(uint32_t* r, uint32_t addr) {
    asm volatile("ldmatrix.sync.aligned.m8n8.x4.trans.shared.b16 {%0,%1,%2,%3}, [%4];"
                 : "=r"(r[0]), "=r"(r[1]), "=r"(r[2]), "=r"(r[3]) : "r"(addr));
}
__device__ __forceinline__ void mma_bf16(float* d, const uint32_t* a, const uint32_t* b) {
    asm volatile("mma.sync.aligned.m16n8k16.row.col.f32.bf16.bf16.f32 "
                 "{%0,%1,%2,%3}, {%4,%5,%6,%7}, {%8,%9}, {%0,%1,%2,%3};"
                 : "+f"(d[0]), "+f"(d[1]), "+f"(d[2]), "+f"(d[3])
                 : "r"(a[0]), "r"(a[1]), "r"(a[2]), "r"(a[3]), "r"(b[0]), "r"(b[1]));
}
__device__ __forceinline__ void split2(float v0, float v1, uint32_t& hi, uint32_t& lo) {
    bf162 hb = __float22bfloat162_rn(make_float2(v0, v1));
    float2 hf = __bfloat1622float2(hb);
    bf162 lb = __float22bfloat162_rn(make_float2(v0 - hf.x, v1 - hf.y));
    hi = *(uint32_t*)&hb;
    lo = *(uint32_t*)&lb;
}

// ---------------- fp32 -> (hi,lo) bf16 split --------------------------------
__global__ void cvt_split(const float* __restrict__ x, bf16* __restrict__ h,
                          bf16* __restrict__ l, int n4)
{
    int i = blockIdx.x * blockDim.x + threadIdx.x;
    if (i >= n4) return;
    float4 v = ((const float4*)x)[i];
    float vs[4] = {v.x, v.y, v.z, v.w};
    #pragma unroll
    for (int j = 0; j < 4; j++) {
        bf16 hb = __float2bfloat16(vs[j]);
        h[i*4+j] = hb;
        l[i*4+j] = __float2bfloat16(vs[j] - __bfloat162float(hb));
    }
}

// ---------------- batched W[K,N] -> Wt[N,K] hi/lo split (z picks matrix) ----
__global__ void transpose_split4(const float* __restrict__ W0, const float* __restrict__ W1,
                                 const float* __restrict__ W2, const float* __restrict__ W3)
{
    __shared__ float t[32][33];
    int z = blockIdx.z;
    const float* W = z == 0 ? W0 : z == 1 ? W1 : z == 2 ? W2 : W3;
    bf16* Th = z == 0 ? g_wqh : z == 1 ? g_wkh : z == 2 ? g_wvh : g_woh;
    bf16* Tl = z == 0 ? g_wql : z == 1 ? g_wkl : z == 2 ? g_wvl : g_wol;

    int bx = blockIdx.x * 32, by = blockIdx.y * 32;
    int tx = threadIdx.x, ty = threadIdx.y;
    #pragma unroll
    for (int i = 0; i < 4; i++)
        t[ty + i*8][tx] = W[(size_t)(by + ty + i*8) * D_ + bx + tx];
    __syncthreads();
    #pragma unroll
    for (int i = 0; i < 4; i++) {
        float vv = t[tx][ty + i*8];
        bf16 hb = __float2bfloat16(vv);
        size_t o = (size_t)(bx + ty + i*8) * D_ + by + tx;
        Th[o] = hb;
        Tl[o] = __float2bfloat16(vv - __bfloat162float(hb));
    }
}

// ---------------- shared GEMM body: C = A @ B^T (+bias), split-bf16 ---------
#define NCHUNK 16
#define STAGE_BYTES 65536
template<bool OUT_F32>
__device__ __forceinline__ void gemm_body(
    const bf16* __restrict__ Ah, const bf16* __restrict__ Al,
    const bf16* __restrict__ Bh, const bf16* __restrict__ Bl,
    const float* __restrict__ bias, float* __restrict__ Cf,
    bf16* __restrict__ Ch, bf16* __restrict__ Cl, char* smem)
{
    uint32_t sb = s2u(smem);
    int tid = threadIdx.x, wid = tid >> 5, lane = tid & 31;
    int wr = wid >> 2, wc = wid & 3;
    int rowBase = blockIdx.y * 128, colBase = blockIdx.x * 128;

    const bf16* bases[4] = {
        Ah + (size_t)rowBase * D_, Al + (size_t)rowBase * D_,
        Bh + (size_t)colBase * D_, Bl + (size_t)colBase * D_ };

    #define LOAD_CHUNK(c_, st_) do { \
        int k0_ = (c_) * 64; \
        uint32_t d0_ = sb + (st_) * STAGE_BYTES; \
        _Pragma("unroll") \
        for (int t_ = 0; t_ < 4; t_++) { \
            const bf16* s_ = bases[t_]; \
            _Pragma("unroll") \
            for (int i_ = 0; i_ < 4; i_++) { \
                int idx_ = tid + i_ * 256; \
                int rr_ = idx_ >> 3, gq_ = idx_ & 7; \
                uint32_t dd_ = d0_ + t_ * 16384 + rr_ * 128 + ((gq_ ^ (rr_ & 7)) << 4); \
                CPA16(dd_, s_ + (size_t)rr_ * D_ + k0_ + gq_ * 8); \
            } \
        } \
        CPC(); \
    } while (0)

    LOAD_CHUNK(0, 0);
    LOAD_CHUNK(1, 1);

    float acc[4][4][4] = {};

    for (int c = 0; c < NCHUNK; c++) {
        if (c < NCHUNK - 1) CPW(1); else CPW(0);
        __syncthreads();
        if (c + 2 < NCHUNK) LOAD_CHUNK(c + 2, (c + 2) % 3);

        uint32_t stg = sb + (c % 3) * STAGE_BYTES;

        #pragma unroll
        for (int ks = 0; ks < 4; ks++) {
            uint32_t a_hi[4][4], a_lo[4][4];
            #pragma unroll
            for (int mi = 0; mi < 4; mi++) {
                int row = wr * 64 + mi * 16 + (lane & 15);
                int kg  = ks * 2 + (lane >> 4);
                uint32_t addr = stg + row * 128 + ((kg ^ (row & 7)) << 4);
                ldm_x4(a_hi[mi], addr);
                ldm_x4(a_lo[mi], addr + 16384);
            }
            uint32_t b_hi[2][4], b_lo[2][4];
            #pragma unroll
            for (int nj = 0; nj < 2; nj++) {
                int rowb = wc * 32 + nj * 16 + (lane & 7) + ((lane & 16) ? 8 : 0);
                int kg   = ks * 2 + ((lane >> 3) & 1);
                uint32_t addr = stg + 32768 + rowb * 128 + ((kg ^ (rowb & 7)) << 4);
                ldm_x4(b_hi[nj], addr);
                ldm_x4(b_lo[nj], addr + 16384);
            }
            #pragma unroll
            for (int mi = 0; mi < 4; mi++)
                #pragma unroll
                for (int ni = 0; ni < 4; ni++) {
                    const uint32_t* bh = &b_hi[ni >> 1][(ni & 1) * 2];
                    const uint32_t* bl = &b_lo[ni >> 1][(ni & 1) * 2];
                    mma_bf16(acc[mi][ni], a_hi[mi], bh);
                    mma_bf16(acc[mi][ni], a_hi[mi], bl);
                    mma_bf16(acc[mi][ni], a_lo[mi], bh);
                }
        }
    }

    #pragma unroll
    for (int ni = 0; ni < 4; ni++) {
        int col = colBase + wc * 32 + ni * 8 + (lane & 3) * 2;
        float2 bb = bias ? *(const float2*)&bias[col] : make_float2(0.f, 0.f);
        #pragma unroll
        for (int mi = 0; mi < 4; mi++) {
            int row = rowBase + wr * 64 + mi * 16 + (lane >> 2);
            float v00 = acc[mi][ni][0] + bb.x, v01 = acc[mi][ni][1] + bb.y;
            float v10 = acc[mi][ni][2] + bb.x, v11 = acc[mi][ni][3] + bb.y;
            if (OUT_F32) {
                *(float2*)&Cf[(size_t)row * D_ + col]       = make_float2(v00, v01);
                *(float2*)&Cf[(size_t)(row + 8) * D_ + col] = make_float2(v10, v11);
            } else {
                uint32_t h0, l0, h1, l1;
                split2(v00, v01, h0, l0);
                split2(v10, v11, h1, l1);
                *(uint32_t*)&Ch[(size_t)row * D_ + col]       = h0;
                *(uint32_t*)&Cl[(size_t)row * D_ + col]       = l0;
                *(uint32_t*)&Ch[(size_t)(row + 8) * D_ + col] = h1;
                *(uint32_t*)&Cl[(size_t)(row + 8) * D_ + col] = l1;
            }
        }
    }
}

// fused Q/K/V projection: blockIdx.z selects weight/bias/output
__global__ void __launch_bounds__(256, 1)
gemm_qkv(const float* __restrict__ bq, const float* __restrict__ bv)
{
    extern __shared__ char smem[];
    int z = blockIdx.z;
    const bf16* Bh = z == 0 ? g_wqh : z == 1 ? g_wkh : g_wvh;
    const bf16* Bl = z == 0 ? g_wql : z == 1 ? g_wkl : g_wvl;
    const float* bias = z == 0 ? bq : z == 1 ? (const float*)nullptr : bv;
    bf16* Ch = z == 0 ? g_qh : z == 1 ? g_kh : g_vh;
    bf16* Cl = z == 0 ? g_ql : z == 1 ? g_kl : g_vl;
    gemm_body<false>(g_xh, g_xl, Bh, Bl, bias, nullptr, Ch, Cl, smem);
}

// output projection: fp32 out
__global__ void __launch_bounds__(256, 1)
gemm_o(const float* __restrict__ bo, float* __restrict__ out)
{
    extern __shared__ char smem[];
    gemm_body<true>(g_ah, g_al, g_woh, g_wol, bo, out, nullptr, nullptr, smem);
}

// ---------------------------------------------------------------------------
// Tensor-core flash attention. CTA = 64 q-rows x one (b,h), 128 threads
// (4 warps x m16n64). 113KB smem -> 2 CTAs/SM so softmax overlaps MMAs
// across CTAs. K/V 64-key tiles hi/lo, 3-stage cp.async pipeline.
// ---------------------------------------------------------------------------
#define FA_QL   8192
#define FA_STG  16384          // 3 stages x 32768 (KH,KL,VH,VL 8KB each)
#define FA_TB   114688         // float[2][128]
#define FA_SMEM (114688 + 2*128*4)
#define NKT     (S_/64)

__global__ void __launch_bounds__(128)
flash_mma(const bf16* __restrict__ qh, const bf16* __restrict__ ql,
          const bf16* __restrict__ kh, const bf16* __restrict__ kl,
          const bf16* __restrict__ vh, const bf16* __restrict__ vl,
          const float* __restrict__ pb,
          bf16* __restrict__ oh, bf16* __restrict__ ol)
{
    extern __shared__ char smem[];
    uint32_t sbase = s2u(smem);
    float* tb = (float*)(smem + FA_TB);

    int tid = threadIdx.x, w = tid >> 5, lane = tid & 31;
    int bh = blockIdx.y, b = bh >> 4, h = bh & 15;
    int q0 = blockIdx.x * 64;

    const float LOG2E = 1.4426950408889634f;
    const float c1L = 0.4785533905932738f * LOG2E;
    const float c2L = 0.3535533905932738f * LOG2E;

    size_t toff = (size_t)(b * S_) * D_ + h * HD_;
    const bf16* kvp[4] = {kh + toff, kl + toff, vh + toff, vl + toff};
    const bf16* qp[2]  = {qh + toff, ql + toff};

    // ---- Q tile (64 rows x 64d, hi/lo) ----
    #pragma unroll
    for (int t = 0; t < 2; t++) {
        #pragma unroll
        for (int i = 0; i < 4; i++) {
            int idx = tid + i * 128;          // 512 granules per array
            int r = idx >> 3, g = idx & 7;
            uint32_t dd = sbase + t * 8192 + r * 128 + ((g ^ (r & 7)) << 4);
            CPA16(dd, qp[t] + (size_t)(q0 + r) * D_ + g * 8);
        }
    }
    #define LOAD_KV(c_, st_) do { \
        int kt_ = (c_) * 64; \
        uint32_t d0_ = sbase + FA_STG + (st_) * 32768; \
        _Pragma("unroll") \
        for (int t_ = 0; t_ < 4; t_++) { \
            _Pragma("unroll") \
            for (int i_ = 0; i_ < 4; i_++) { \
                int idx_ = tid + i_ * 128; \
                int r_ = idx_ >> 3, g_ = idx_ & 7; \
                uint32_t dd_ = d0_ + t_ * 8192 + r_ * 128 + ((g_ ^ (r_ & 7)) << 4); \
                CPA16(dd_, kvp[t_] + (size_t)(kt_ + r_) * D_ + g_ * 8); \
            } \
        } \
        CPC(); \
    } while (0)

    LOAD_KV(0, 0);
    LOAD_KV(1, 1);

    if (tid < 127) {
        int rel = q0 - 0 + (tid - 63);
        rel = min(max(rel, -(MAXD - 1)), MAXD - 1) + (MAXD - 1);
        tb[tid] = c2L * __ldg(&pb[rel * H_ + h]);
    }

    uint32_t qa_h[4][4], qa_l[4][4];
    float o[8][4] = {};
    float m0 = -1e30f, m1 = -1e30f, l0 = 0.f, l1 = 0.f;

    for (int c = 0; c < NKT; c++) {
        if (c < NKT - 1) CPW(1); else CPW(0);
        __syncthreads();

        if (c == 0) {
            #pragma unroll
            for (int ks = 0; ks < 4; ks++) {
                int row = w * 16 + (lane & 15);
                int kg  = ks * 2 + (lane >> 4);
                uint32_t addr = sbase + row * 128 + ((kg ^ (row & 7)) << 4);
                ldm_x4(qa_h[ks], addr);
                ldm_x4(qa_l[ks], addr + 8192);
            }
        }
        if (c + 2 < NKT) LOAD_KV(c + 2, (c + 2) % 3);
        if (c + 1 < NKT && tid < 127) {
            int rel = q0 - (c + 1) * 64 + (tid - 63);
            rel = min(max(rel, -(MAXD - 1)), MAXD - 1) + (MAXD - 1);
            tb[((c + 1) & 1) * 128 + tid] = c2L * __ldg(&pb[rel * H_ + h]);
        }

        uint32_t stg = sbase + FA_STG + (c % 3) * 32768;
        const float* tbc = tb + (c & 1) * 128;

        // ---- S = Q K^T (3 split passes) ----
        float s[8][4] = {};
        #pragma unroll
        for (int ks = 0; ks < 4; ks++) {
            uint32_t bK_h[4][4], bK_l[4][4];
            #pragma unroll
            for (int nj = 0; nj < 4; nj++) {
                int rowb = nj * 16 + (lane & 7) + ((lane & 16) ? 8 : 0);
                int kg   = ks * 2 + ((lane >> 3) & 1);
                uint32_t addr = stg + rowb * 128 + ((kg ^ (rowb & 7)) << 4);
                ldm_x4(bK_h[nj], addr);
                ldm_x4(bK_l[nj], addr + 8192);
            }
            #pragma unroll
            for (int ni = 0; ni < 8; ni++) {
                const uint32_t* bh2 = &bK_h[ni >> 1][(ni & 1) * 2];
                const uint32_t* bl2 = &bK_l[ni >> 1][(ni & 1) * 2];
                mma_bf16(s[ni], qa_h[ks], bh2);
                mma_bf16(s[ni], qa_h[ks], bl2);
                mma_bf16(s[ni], qa_l[ks], bh2);
            }
        }

        // ---- bias + online softmax (exp2 domain) ----
        int i0 = w * 16 + (lane >> 2);
        int jb = 2 * (lane & 3);
        float t0 = -1e30f, t1 = -1e30f;
        #pragma unroll
        for (int ni = 0; ni < 8; ni++) {
            int tix = i0 - (8 * ni + jb) + 63;
            s[ni][0] = fmaf(c1L, s[ni][0], tbc[tix]);
            s[ni][1] = fmaf(c1L, s[ni][1], tbc[tix - 1]);
            s[ni][2] = fmaf(c1L, s[ni][2], tbc[tix + 8]);
            s[ni][3] = fmaf(c1L, s[ni][3], tbc[tix + 7]);
            t0 = fmaxf(t0, fmaxf(s[ni][0], s[ni][1]));
            t1 = fmaxf(t1, fmaxf(s[ni][2], s[ni][3]));
        }
        t0 = fmaxf(t0, __shfl_xor_sync(0xffffffffu, t0, 1));
        t0 = fmaxf(t0, __shfl_xor_sync(0xffffffffu, t0, 2));
        t1 = fmaxf(t1, __shfl_xor_sync(0xffffffffu, t1, 1));
        t1 = fmaxf(t1, __shfl_xor_sync(0xffffffffu, t1, 2));
        float m0n = fmaxf(m0, t0), m1n = fmaxf(m1, t1);
        float cr0 = exp2f(m0 - m0n), cr1 = exp2f(m1 - m1n);
        m0 = m0n; m1 = m1n;

        float ls0 = 0.f, ls1 = 0.f;
        #pragma unroll
        for (int ni = 0; ni < 8; ni++) {
            s[ni][0] = exp2f(s[ni][0] - m0);
            s[ni][1] = exp2f(s[ni][1] - m0);
            s[ni][2] = exp2f(s[ni][2] - m1);
            s[ni][3] = exp2f(s[ni][3] - m1);
            ls0 += s[ni][0] + s[ni][1];
            ls1 += s[ni][2] + s[ni][3];
            o[ni][0] *= cr0; o[ni][1] *= cr0;
            o[ni][2] *= cr1; o[ni][3] *= cr1;
        }
        l0 = l0 * cr0 + ls0;
        l1 = l1 * cr1 + ls1;

        // ---- O += P V (3 split passes) ----
        #pragma unroll
        for (int t = 0; t < 4; t++) {
            uint32_t a_h[4], a_l[4];
            split2(s[2*t][0],   s[2*t][1],   a_h[0], a_l[0]);
            split2(s[2*t][2],   s[2*t][3],   a_h[1], a_l[1]);
            split2(s[2*t+1][0], s[2*t+1][1], a_h[2], a_l[2]);
            split2(s[2*t+1][2], s[2*t+1][3], a_h[3], a_l[3]);

            uint32_t bV_h[4][4], bV_l[4][4];
            #pragma unroll
            for (int vj = 0; vj < 4; vj++) {
                int rowv = t * 16 + (lane & 7) + ((lane & 8) ? 8 : 0);
                int gq   = 2 * vj + ((lane >> 4) & 1);
                uint32_t addr = stg + 16384 + rowv * 128 + ((gq ^ (rowv & 7)) << 4);
                ldm_x4_t(bV_h[vj], addr);
                ldm_x4_t(bV_l[vj], addr + 8192);
            }
            #pragma unroll
            for (int ni = 0; ni < 8; ni++) {
                const uint32_t* bh2 = &bV_h[ni >> 1][(ni & 1) * 2];
                const uint32_t* bl2 = &bV_l[ni >> 1][(ni & 1) * 2];
                mma_bf16(o[ni], a_h, bh2);
                mma_bf16(o[ni], a_l, bh2);
                mma_bf16(o[ni], a_h, bl2);
            }
        }
    }

    l0 += __shfl_xor_sync(0xffffffffu, l0, 1);
    l0 += __shfl_xor_sync(0xffffffffu, l0, 2);
    l1 += __shfl_xor_sync(0xffffffffu, l1, 1);
    l1 += __shfl_xor_sync(0xffffffffu, l1, 2);
    float inv0 = 1.f / l0, inv1 = 1.f / l1;

    int row0 = b * S_ + q0 + w * 16 + (lane >> 2);
    #pragma unroll
    for (int ni = 0; ni < 8; ni++) {
        int col = h * HD_ + 8 * ni + 2 * (lane & 3);
        uint32_t h0, lo0, h1, lo1;
        split2(o[ni][0] * inv0, o[ni][1] * inv0, h0, lo0);
        split2(o[ni][2] * inv1, o[ni][3] * inv1, h1, lo1);
        *(uint32_t*)&oh[(size_t)row0 * D_ + col]       = h0;
        *(uint32_t*)&ol[(size_t)row0 * D_ + col]       = lo0;
        *(uint32_t*)&oh[(size_t)(row0 + 8) * D_ + col] = h1;
        *(uint32_t*)&ol[(size_t)(row0 + 8) * D_ + col] = lo1;
    }
}

// ---------------------------------------------------------------------------
extern "C" void kernel_launch(void* const* d_in, const int* in_sizes, int n_in,
                              void* d_out, int out_size)
{
    const float* x  = (const float*)d_in[0];
    const float* Wq = (const float*)d_in[1];
    const float* bq = (const float*)d_in[2];
    const float* Wk = (const float*)d_in[3];
    const float* Wv = (const float*)d_in[4];
    const float* bv = (const float*)d_in[5];
    const float* Wo = (const float*)d_in[6];
    const float* bo = (const float*)d_in[7];
    const float* pb = (const float*)d_in[8];
    float* out = (float*)d_out;

    bf16 *xh, *xl, *qh, *ql, *kh, *kl, *vh, *vl, *ah, *al;
    cudaGetSymbolAddress((void**)&xh, g_xh); cudaGetSymbolAddress((void**)&xl, g_xl);
    cudaGetSymbolAddress((void**)&qh, g_qh); cudaGetSymbolAddress((void**)&ql, g_ql);
    cudaGetSymbolAddress((void**)&kh, g_kh); cudaGetSymbolAddress((void**)&kl, g_kl);
    cudaGetSymbolAddress((void**)&vh, g_vh); cudaGetSymbolAddress((void**)&vl, g_vl);
    cudaGetSymbolAddress((void**)&ah, g_ah); cudaGetSymbolAddress((void**)&al, g_al);

    const int M = B_ * S_;
    const int NELEM4 = M * D_ / 4;

    cvt_split<<<NELEM4 / 256, 256>>>(x, xh, xl, NELEM4);
    dim3 tGrid(D_ / 32, D_ / 32, 4), tBlk(32, 8);
    transpose_split4<<<tGrid, tBlk>>>(Wq, Wk, Wv, Wo);

    int gsmem = 3 * STAGE_BYTES;
    cudaFuncSetAttribute(gemm_qkv, cudaFuncAttributeMaxDynamicSharedMemorySize, gsmem);
    cudaFuncSetAttribute(gemm_o,   cudaFuncAttributeMaxDynamicSharedMemorySize, gsmem);

    dim3 qkvGrid(D_ / 128, M / 128, 3);          // (8, 32, 3)
    gemm_qkv<<<qkvGrid, 256, gsmem>>>(bq, bv);

    cudaFuncSetAttribute(flash_mma, cudaFuncAttributeMaxDynamicSharedMemorySize, FA_SMEM);
    dim3 fGrid(S_ / 64, B_ * H_);                // (32, 32)
    flash_mma<<<fGrid, 128, FA_SMEM>>>(qh, ql, kh, kl, vh, vl, pb, ah, al);

    dim3 oGrid(D_ / 128, M / 128);               // (8, 32)
    gemm_o<<<oGrid, 256, gsmem>>>(bo, out);
}